// round 4
// baseline (speedup 1.0000x reference)
#include <cuda_runtime.h>
#include <math.h>

// Problem shape (fixed by setup_inputs): X (32, 64, 25, 2, 16, 16) fp32.
#define S_N     32
#define TVM     3200
#define NE      256
#define CHUNKS  32
#define CHUNK_M 100
#define NW      16      // warps in k_chain

// ---------------- device scratch (no allocations allowed) ----------------
__device__ float g_partial[S_N * CHUNKS * NE];
__device__ float g_xmean[S_N * NE];
__device__ float g_C[NE];

// =========================================================================
// K1: partial reduction of X. grid (32,32), 256 thr; 100 matrices / block.
// =========================================================================
__global__ __launch_bounds__(256) void k_partial(const float* __restrict__ X) {
    int s = blockIdx.x, c = blockIdx.y, t = threadIdx.x;
    const float* p = X + ((size_t)s * TVM + (size_t)c * CHUNK_M) * NE + t;
    float a0 = 0.f, a1 = 0.f, a2 = 0.f, a3 = 0.f;
#pragma unroll
    for (int m = 0; m < CHUNK_M; m += 4) {
        a0 += p[(size_t)m * NE];
        a1 += p[(size_t)(m + 1) * NE];
        a2 += p[(size_t)(m + 2) * NE];
        a3 += p[(size_t)(m + 3) * NE];
    }
    g_partial[(s * CHUNKS + c) * NE + t] = (a0 + a1) + (a2 + a3);
}

// =========================================================================
// K2: per-sample means. grid 32, 256 thr.
// =========================================================================
__global__ __launch_bounds__(256) void k_samplemean() {
    int b = blockIdx.x, t = threadIdx.x;
    float acc = 0.f;
#pragma unroll 8
    for (int c = 0; c < CHUNKS; ++c) acc += g_partial[(b * CHUNKS + c) * NE + t];
    g_xmean[b * NE + t] = acc * (1.f / (float)TVM);
}

// =========================================================================
// Warp-level 16x16 toolkit. Matrix = 256 contiguous floats in shared
// (row-major, stride 16). Elementwise ownership: idx = q*32 + lane
// (bank-conflict-free). All iteration counts derived ONCE from the initial
// error norm — no per-iteration convergence reductions.
// =========================================================================
__device__ __forceinline__ float wsum32(float v) {
#pragma unroll
    for (int o = 16; o; o >>= 1) v += __shfl_xor_sync(0xffffffffu, v, o);
    return v;
}
__device__ __forceinline__ float wmax32(float v) {
#pragma unroll
    for (int o = 16; o; o >>= 1) v = fmaxf(v, __shfl_xor_sync(0xffffffffu, v, o));
    return v;
}
__device__ __forceinline__ float w_trace16(const float* A, int lane) {
    float v = (lane < 16) ? A[lane * 17] : 0.f;
    return wsum32(v);
}

// C = A * B. Lane computes half-row: i = lane>>1, cols jb..jb+7.
// Safe even if C aliases A or B (reads done before the store sync).
__device__ __forceinline__ void wmm16(float* C, const float* A, const float* B, int lane) {
    int i = lane >> 1, jb = (lane & 1) << 3;
    const float4* ar = (const float4*)(A + i * 16);
    float4 v0 = ar[0], v1 = ar[1], v2 = ar[2], v3 = ar[3];
    float a[16] = {v0.x, v0.y, v0.z, v0.w, v1.x, v1.y, v1.z, v1.w,
                   v2.x, v2.y, v2.z, v2.w, v3.x, v3.y, v3.z, v3.w};
    float c[8] = {0.f, 0.f, 0.f, 0.f, 0.f, 0.f, 0.f, 0.f};
#pragma unroll
    for (int k = 0; k < 16; ++k) {
        const float4* br = (const float4*)(B + k * 16 + jb);
        float4 b0 = br[0], b1 = br[1];
        float ak = a[k];
        c[0] = fmaf(ak, b0.x, c[0]); c[1] = fmaf(ak, b0.y, c[1]);
        c[2] = fmaf(ak, b0.z, c[2]); c[3] = fmaf(ak, b0.w, c[3]);
        c[4] = fmaf(ak, b1.x, c[4]); c[5] = fmaf(ak, b1.y, c[5]);
        c[6] = fmaf(ak, b1.z, c[6]); c[7] = fmaf(ak, b1.w, c[7]);
    }
    __syncwarp();
    float4* cr = (float4*)(C + i * 16 + jb);
    cr[0] = make_float4(c[0], c[1], c[2], c[3]);
    cr[1] = make_float4(c[4], c[5], c[6], c[7]);
    __syncwarp();
}

// Coupled Newton-Schulz: Y = sqrt(A), Z = invsqrt(A). Iteration count from
// initial ||A/s - I||_F via quadratic convergence model.
__device__ void w_sqrtinv(const float* A, float* Y, float* Z,
                          float* T, float* Y2, float* Z2, int lane) {
    float s = w_trace16(A, lane) * (1.f / 16.f);
    float is0 = 1.f / s, d2 = 0.f;
#pragma unroll
    for (int q = 0; q < 8; ++q) {
        int idx = q * 32 + lane; int r = idx >> 4, c = idx & 15;
        float v = A[idx] * is0 - (r == c ? 1.f : 0.f);
        d2 += v * v;
    }
    d2 = wsum32(d2);
    int n;
    if (d2 >= 0.81f) {          // Gershgorin fallback (not expected on this data)
        float rs = 0.f;
        if (lane < 16) { for (int k = 0; k < 16; ++k) rs += fabsf(A[lane * 16 + k]); }
        rs = wmax32(rs);
        s = rs; is0 = 1.f / s; n = 12;
    } else {
        float cur = sqrtf(d2); n = 0;
        while (cur > 1e-7f && n < 7) { cur = 1.3f * cur * cur; ++n; }
    }
#pragma unroll
    for (int q = 0; q < 8; ++q) {
        int idx = q * 32 + lane; int r = idx >> 4, c = idx & 15;
        Y[idx] = A[idx] * is0;
        Z[idx] = (r == c) ? 1.f : 0.f;
    }
    __syncwarp();
    float* y = Y; float* z = Z; float* y2 = Y2; float* z2 = Z2;
    for (int it = 0; it < n; ++it) {
        wmm16(T, z, y, lane);
#pragma unroll
        for (int q = 0; q < 8; ++q) {
            int idx = q * 32 + lane; int r = idx >> 4, c = idx & 15;
            T[idx] = 0.5f * ((r == c ? 3.f : 0.f) - T[idx]);
        }
        __syncwarp();
        wmm16(y2, y, T, lane);
        wmm16(z2, T, z, lane);
        float* tm = y; y = y2; y2 = tm;
        tm = z; z = z2; z2 = tm;
    }
    float fs = sqrtf(s), fi = rsqrtf(s);
    float ry[8], rz[8];
#pragma unroll
    for (int q = 0; q < 8; ++q) { int idx = q * 32 + lane; ry[q] = y[idx] * fs; rz[q] = z[idx] * fi; }
    __syncwarp();
#pragma unroll
    for (int q = 0; q < 8; ++q) { int idx = q * 32 + lane; Y[idx] = ry[q]; Z[idx] = rz[q]; }
    __syncwarp();
}

// logm(B) in place: logm(B) = ln(s) I + Mercator(B/s - I). Term count from d.
__device__ void w_logm(float* B, float* t1, float* t2, float* t3,
                       float* t4, float* t5, int lane) {
    int jsq = 0; float s, d2;
    for (;;) {
        s = w_trace16(B, lane) * (1.f / 16.f);
        float is = 1.f / s; d2 = 0.f;
#pragma unroll
        for (int q = 0; q < 8; ++q) {
            int idx = q * 32 + lane; int r = idx >> 4, c = idx & 15;
            float v = B[idx] * is - (r == c ? 1.f : 0.f);
            t1[idx] = v; d2 += v * v;
        }
        __syncwarp();
        d2 = wsum32(d2);
        if (d2 <= 0.25f || jsq >= 4) break;         // ||E||_F <= 0.5
        w_sqrtinv(B, t2, t3, t4, t5, t1, lane);     // t2 = sqrt(B)
        float r8[8];
#pragma unroll
        for (int q = 0; q < 8; ++q) r8[q] = t2[q * 32 + lane];
        __syncwarp();
#pragma unroll
        for (int q = 0; q < 8; ++q) B[q * 32 + lane] = r8[q];
        __syncwarp();
        ++jsq;
    }
    float d = sqrtf(d2);
    int nt = 1; { float r = d; while (r > 1e-7f && nt < 24) { r *= d; ++nt; } }
    float lns = logf(s);
#pragma unroll
    for (int q = 0; q < 8; ++q) {
        int idx = q * 32 + lane; int r = idx >> 4, c = idx & 15;
        float v = t1[idx];
        B[idx] = (r == c ? lns : 0.f) + v;
        t2[idx] = v;
    }
    __syncwarp();
    float* P = t2; float* P2 = t3; float sg = 1.f;
    for (int k = 2; k <= nt; ++k) {
        wmm16(P2, P, t1, lane);
        sg = -sg; float cf = sg / (float)k;
#pragma unroll
        for (int q = 0; q < 8; ++q) { int idx = q * 32 + lane; B[idx] += cf * P2[idx]; }
        __syncwarp();
        float* tm = P; P = P2; P2 = tm;
    }
    if (jsq) {
        float f = (float)(1 << jsq);
#pragma unroll
        for (int q = 0; q < 8; ++q) B[q * 32 + lane] *= f;
        __syncwarp();
    }
}

// R = expm(A): expm(A) = e^c expm(A - cI), c = tr/16. A preserved.
__device__ void w_expm(const float* A, float* R, float* t1, float* t2, float* t3, int lane) {
    float c0 = w_trace16(A, lane) * (1.f / 16.f);
    float d2 = 0.f;
#pragma unroll
    for (int q = 0; q < 8; ++q) {
        int idx = q * 32 + lane; int r = idx >> 4, c = idx & 15;
        float v = A[idx] - (r == c ? c0 : 0.f);
        t1[idx] = v; d2 += v * v;
    }
    __syncwarp();
    d2 = wsum32(d2);
    int j = 0; float sc = 1.f;
    while (d2 > 0.25f && j < 20) { sc *= 0.5f; d2 *= 0.25f; ++j; }
    if (j) {
#pragma unroll
        for (int q = 0; q < 8; ++q) t1[q * 32 + lane] *= sc;
        __syncwarp();
    }
    float d = sqrtf(d2);
    int nt = 1; { float r = d; while (r > 1e-7f && nt < 14) { ++nt; r *= d / (float)nt; } }
    float ec = expf(c0 * sc);
#pragma unroll
    for (int q = 0; q < 8; ++q) {
        int idx = q * 32 + lane; int r = idx >> 4, c = idx & 15;
        float v = t1[idx];
        R[idx] = (r == c ? 1.f : 0.f) + v;
        t2[idx] = v;
    }
    __syncwarp();
    float* P = t2; float* P2 = t3;
    for (int k = 2; k <= nt; ++k) {
        wmm16(P2, P, t1, lane);
        float ik = 1.f / (float)k;
#pragma unroll
        for (int q = 0; q < 8; ++q) { int idx = q * 32 + lane; float v = P2[idx] * ik; P2[idx] = v; R[idx] += v; }
        __syncwarp();
        float* tm = P; P = P2; P2 = tm;
    }
#pragma unroll
    for (int q = 0; q < 8; ++q) R[q * 32 + lane] *= ec;
    __syncwarp();
    for (int q2 = 0; q2 < j; ++q2) {
        wmm16(t2, R, R, lane);
#pragma unroll
        for (int q = 0; q < 8; ++q) R[q * 32 + lane] = t2[q * 32 + lane];
        __syncwarp();
    }
}

// =========================================================================
// K3: entire small-matrix chain, one block of 512 threads (16 warps).
//  s0 G = mean_b(xmean); load rm
//  s1 warp0: (Gs,Gi)=sqrt/invsqrt(G) || warp1: (As,Ai)=sqrt/invsqrt(rm)
//  s2 warp w: L_w + L_{w+16} = logm(Gi xmean Gi), accumulated in B0
//  s3 Lbar;  s4 warp0: mean = Gs expm(Lbar) Gs
//  s5 warp0: C = invsqrt(mean) -> g_C || warp1: geodesic(rm, mean, .1) -> tail
// =========================================================================
__global__ __launch_bounds__(512, 1) void k_chain(const float* __restrict__ rm,
                                                  float* __restrict__ out_tail,
                                                  int write_tail) {
    extern __shared__ float smem[];
    int t = threadIdx.x, w = t >> 5, lane = t & 31;
    float* wb = smem + w * (6 * 256);
    float* B0 = wb;           float* B1 = wb + 256;  float* B2 = wb + 512;
    float* B3 = wb + 768;     float* B4 = wb + 1024; float* B5 = wb + 1280;
    float* sGs = smem + NW * 6 * 256;
    float* sGi = sGs + 256; float* sAs = sGs + 512; float* sAi = sGs + 768;
    float* sMean = sGs + 1024; float* sLbar = sGs + 1280;

    // s0
    if (t < 256) {
        float acc = 0.f;
#pragma unroll 8
        for (int b = 0; b < S_N; ++b) acc += g_xmean[b * NE + t];
        smem[t] = acc * (1.f / (float)S_N);   // warp0's B0 = G
        smem[1536 + t] = rm[t];               // warp1's B0 = running_mean
    }
    __syncthreads();

    // s1
    if (w == 0) {
        w_sqrtinv(B0, B1, B2, B3, B4, B5, lane);
#pragma unroll
        for (int q = 0; q < 8; ++q) { int idx = q * 32 + lane; sGs[idx] = B1[idx]; sGi[idx] = B2[idx]; }
    } else if (w == 1) {
        w_sqrtinv(B0, B1, B2, B3, B4, B5, lane);
#pragma unroll
        for (int q = 0; q < 8; ++q) { int idx = q * 32 + lane; sAs[idx] = B1[idx]; sAi[idx] = B2[idx]; }
    }
    __syncthreads();

    // s2: two logms per warp, accumulated into B0
    float lstash[8];
#pragma unroll
    for (int q = 0; q < 8; ++q) { int idx = q * 32 + lane; B1[idx] = g_xmean[w * NE + idx]; }
    __syncwarp();
    wmm16(B2, sGi, B1, lane);
    wmm16(B0, B2, sGi, lane);
    w_logm(B0, B1, B2, B3, B4, B5, lane);
#pragma unroll
    for (int q = 0; q < 8; ++q) lstash[q] = B0[q * 32 + lane];
    __syncwarp();
#pragma unroll
    for (int q = 0; q < 8; ++q) { int idx = q * 32 + lane; B1[idx] = g_xmean[(w + NW) * NE + idx]; }
    __syncwarp();
    wmm16(B2, sGi, B1, lane);
    wmm16(B0, B2, sGi, lane);
    w_logm(B0, B1, B2, B3, B4, B5, lane);
#pragma unroll
    for (int q = 0; q < 8; ++q) B0[q * 32 + lane] += lstash[q];
    __syncwarp();
    __syncthreads();

    // s3
    if (t < 256) {
        float acc = 0.f;
#pragma unroll
        for (int w2 = 0; w2 < NW; ++w2) acc += smem[w2 * 1536 + t];
        sLbar[t] = acc * (1.f / (float)S_N);
    }
    __syncthreads();

    // s4
    if (w == 0) {
        w_expm(sLbar, B1, B2, B3, B4, lane);    // B1 = expm(Lbar)
        wmm16(B2, sGs, B1, lane);
        wmm16(sMean, B2, sGs, lane);
    }
    __syncthreads();

    // s5
    if (w == 0) {
        w_sqrtinv(sMean, B0, B1, B2, B3, B4, lane);   // B1 = invsqrt(mean)
#pragma unroll
        for (int q = 0; q < 8; ++q) { int idx = q * 32 + lane; g_C[idx] = B1[idx]; }
    } else if (w == 1) {
        wmm16(B1, sAi, sMean, lane);
        wmm16(B2, B1, sAi, lane);                     // M = Ai mean Ai
        w_logm(B2, B0, B1, B3, B4, B5, lane);
#pragma unroll
        for (int q = 0; q < 8; ++q) B2[q * 32 + lane] *= 0.1f;
        __syncwarp();
        w_expm(B2, B0, B1, B3, B4, lane);             // B0 = M^0.1
        wmm16(B1, sAs, B0, lane);
        wmm16(B3, B1, sAs, lane);                     // new running mean
        if (write_tail) {
#pragma unroll
            for (int q = 0; q < 8; ++q) { int idx = q * 32 + lane; out_tail[idx] = B3[idx]; }
        }
    }
}

// =========================================================================
// K4: Y = C * X * C for all 102,400 matrices. Packed f32x2 FMA, float4 I/O.
// =========================================================================
typedef unsigned long long u64;
__device__ __forceinline__ u64 pk2(float lo, float hi) {
    u64 r; asm("mov.b64 %0, {%1, %2};" : "=l"(r) : "f"(lo), "f"(hi)); return r;
}
__device__ __forceinline__ void upk2(u64 v, float& lo, float& hi) {
    asm("mov.b64 {%0, %1}, %2;" : "=f"(lo), "=f"(hi) : "l"(v));
}
__device__ __forceinline__ u64 ffma2(u64 a, u64 b, u64 c) {
    u64 d; asm("fma.rn.f32x2 %0, %1, %2, %3;" : "=l"(d) : "l"(a), "l"(b), "l"(c)); return d;
}

#define MPB  16
#define ZPAD 20

__global__ __launch_bounds__(256) void k_transform(const float* __restrict__ X,
                                                   float* __restrict__ Y) {
    __shared__ float Cs[256];
    __shared__ float Zs[MPB * 16 * ZPAD];
    int t = threadIdx.x;
    Cs[t] = g_C[t];
    int m = t >> 4, i = t & 15;
    size_t base = (size_t)blockIdx.x * (MPB * NE) + (size_t)m * NE + (size_t)i * 16;

    float xr[16];
    const float4* xp = (const float4*)(X + base);
#pragma unroll
    for (int q = 0; q < 4; ++q) {
        float4 v = xp[q];
        xr[4 * q] = v.x; xr[4 * q + 1] = v.y; xr[4 * q + 2] = v.z; xr[4 * q + 3] = v.w;
    }
    __syncthreads();

    u64 acc[8];
#pragma unroll
    for (int q = 0; q < 8; ++q) acc[q] = pk2(0.f, 0.f);
#pragma unroll
    for (int k = 0; k < 16; ++k) {
        u64 vv = pk2(xr[k], xr[k]);
        const u64* crow = (const u64*)&Cs[k * 16];
#pragma unroll
        for (int q = 0; q < 8; ++q) acc[q] = ffma2(vv, crow[q], acc[q]);
    }
    float* zr = &Zs[(m * 16 + i) * ZPAD];
#pragma unroll
    for (int q = 0; q < 8; ++q) upk2(acc[q], zr[2 * q], zr[2 * q + 1]);

    float cr[16];
#pragma unroll
    for (int k = 0; k < 16; ++k) cr[k] = Cs[i * 16 + k];
    __syncthreads();

#pragma unroll
    for (int q = 0; q < 8; ++q) acc[q] = pk2(0.f, 0.f);
#pragma unroll
    for (int k = 0; k < 16; ++k) {
        u64 vv = pk2(cr[k], cr[k]);
        const u64* zrow = (const u64*)&Zs[(m * 16 + k) * ZPAD];
#pragma unroll
        for (int q = 0; q < 8; ++q) acc[q] = ffma2(vv, zrow[q], acc[q]);
    }
    float4* yp = (float4*)(Y + base);
#pragma unroll
    for (int q = 0; q < 4; ++q) {
        float4 v;
        upk2(acc[2 * q], v.x, v.y);
        upk2(acc[2 * q + 1], v.z, v.w);
        yp[q] = v;
    }
}

// =========================================================================
extern "C" void kernel_launch(void* const* d_in, const int* in_sizes, int n_in,
                              void* d_out, int out_size) {
    const float* X = (const float*)d_in[0];
    const float* rm = (const float*)d_in[1];
    float* out = (float*)d_out;
    long long n_x = in_sizes[0];           // 26,214,400
    int nmat = (int)(n_x >> 8);            // 102,400
    int write_tail = ((long long)out_size - n_x) >= NE ? 1 : 0;

    const int chain_smem = (NW * 6 * 256 + 6 * 256) * (int)sizeof(float);  // 104,448 B
    cudaFuncSetAttribute(k_chain, cudaFuncAttributeMaxDynamicSharedMemorySize, chain_smem);

    k_partial<<<dim3(S_N, CHUNKS), 256>>>(X);
    k_samplemean<<<S_N, 256>>>();
    k_chain<<<1, 512, chain_smem>>>(rm, out + n_x, write_tail);
    k_transform<<<nmat / MPB, 256>>>(X, out);
}

// round 6
// speedup vs baseline: 1.0818x; 1.0818x over previous
#include <cuda_runtime.h>
#include <math.h>

// Problem shape (fixed by setup_inputs): X (32, 64, 25, 2, 16, 16) fp32.
#define S_N     32
#define TVM     3200
#define NE      256
#define CHUNKS  32
#define CHUNK_M 100

// ---------------- device scratch (no allocations allowed) ----------------
__device__ float g_partial[S_N * CHUNKS * NE];
__device__ float g_xmean[S_N * NE];
__device__ float g_L[S_N * NE];
__device__ float g_Gs[NE], g_Gi[NE];
__device__ float g_As[NE], g_Ai[NE];
__device__ float g_C[NE];

// =========================================================================
// K1: partial reduction of X. grid (32,32), 256 thr; 100 matrices / block.
// float4 loads: thread (g, j) owns float4 column j (of 64), 25 matrices.
// Cross-reduce the 4 row-groups through shared.
// =========================================================================
__global__ __launch_bounds__(256) void k_partial(const float* __restrict__ X) {
    __shared__ float4 red[256];
    int s = blockIdx.x, c = blockIdx.y, t = threadIdx.x;
    int j = t & 63, gsub = t >> 6;                  // 4 row-groups of 25 matrices
    const float4* p = (const float4*)(X + ((size_t)s * TVM + (size_t)c * CHUNK_M) * NE)
                      + (size_t)gsub * 25 * 64 + j;
    float4 a = make_float4(0.f, 0.f, 0.f, 0.f);
#pragma unroll
    for (int m = 0; m < 25; ++m) {
        float4 v = p[(size_t)m * 64];
        a.x += v.x; a.y += v.y; a.z += v.z; a.w += v.w;
    }
    red[t] = a;
    __syncthreads();
    if (t < 64) {
        float4 b0 = red[t], b1 = red[t + 64], b2 = red[t + 128], b3 = red[t + 192];
        float4 r = make_float4((b0.x + b1.x) + (b2.x + b3.x),
                               (b0.y + b1.y) + (b2.y + b3.y),
                               (b0.z + b1.z) + (b2.z + b3.z),
                               (b0.w + b1.w) + (b2.w + b3.w));
        ((float4*)(g_partial + (s * CHUNKS + c) * NE))[t] = r;
    }
}

// =========================================================================
// K2: per-sample means. grid 32, 256 thr.
// =========================================================================
__global__ __launch_bounds__(256) void k_samplemean() {
    int b = blockIdx.x, t = threadIdx.x;
    float acc = 0.f;
#pragma unroll 8
    for (int c = 0; c < CHUNKS; ++c) acc += g_partial[(b * CHUNKS + c) * NE + t];
    g_xmean[b * NE + t] = acc * (1.f / (float)TVM);
}

// =========================================================================
// Warp-level 16x16 toolkit (matrix = 256 contiguous floats, row-major).
// Elementwise ownership idx = q*32 + lane. Iteration counts derived ONCE
// from the initial error norm — no per-iteration convergence reductions.
// =========================================================================
__device__ __forceinline__ float wsum32(float v) {
#pragma unroll
    for (int o = 16; o; o >>= 1) v += __shfl_xor_sync(0xffffffffu, v, o);
    return v;
}
__device__ __forceinline__ float wmax32(float v) {
#pragma unroll
    for (int o = 16; o; o >>= 1) v = fmaxf(v, __shfl_xor_sync(0xffffffffu, v, o));
    return v;
}
__device__ __forceinline__ float w_trace16(const float* A, int lane) {
    float v = (lane < 16) ? A[lane * 17] : 0.f;
    return wsum32(v);
}

// C = A * B. Lane computes half-row: i = lane>>1, cols jb..jb+7.
__device__ __forceinline__ void wmm16(float* C, const float* A, const float* B, int lane) {
    int i = lane >> 1, jb = (lane & 1) << 3;
    const float4* ar = (const float4*)(A + i * 16);
    float4 v0 = ar[0], v1 = ar[1], v2 = ar[2], v3 = ar[3];
    float a[16] = {v0.x, v0.y, v0.z, v0.w, v1.x, v1.y, v1.z, v1.w,
                   v2.x, v2.y, v2.z, v2.w, v3.x, v3.y, v3.z, v3.w};
    float c[8] = {0.f, 0.f, 0.f, 0.f, 0.f, 0.f, 0.f, 0.f};
#pragma unroll
    for (int k = 0; k < 16; ++k) {
        const float4* br = (const float4*)(B + k * 16 + jb);
        float4 b0 = br[0], b1 = br[1];
        float ak = a[k];
        c[0] = fmaf(ak, b0.x, c[0]); c[1] = fmaf(ak, b0.y, c[1]);
        c[2] = fmaf(ak, b0.z, c[2]); c[3] = fmaf(ak, b0.w, c[3]);
        c[4] = fmaf(ak, b1.x, c[4]); c[5] = fmaf(ak, b1.y, c[5]);
        c[6] = fmaf(ak, b1.z, c[6]); c[7] = fmaf(ak, b1.w, c[7]);
    }
    __syncwarp();
    float4* cr = (float4*)(C + i * 16 + jb);
    cr[0] = make_float4(c[0], c[1], c[2], c[3]);
    cr[1] = make_float4(c[4], c[5], c[6], c[7]);
    __syncwarp();
}

// Coupled Newton-Schulz: Y = sqrt(A), Z = invsqrt(A).
__device__ void w_sqrtinv(const float* A, float* Y, float* Z,
                          float* T, float* Y2, float* Z2, int lane) {
    float s = w_trace16(A, lane) * (1.f / 16.f);
    float is0 = 1.f / s, d2 = 0.f;
#pragma unroll
    for (int q = 0; q < 8; ++q) {
        int idx = q * 32 + lane; int r = idx >> 4, c = idx & 15;
        float v = A[idx] * is0 - (r == c ? 1.f : 0.f);
        d2 += v * v;
    }
    d2 = wsum32(d2);
    int n;
    if (d2 >= 0.81f) {
        float rs = 0.f;
        if (lane < 16) { for (int k = 0; k < 16; ++k) rs += fabsf(A[lane * 16 + k]); }
        rs = wmax32(rs);
        s = rs; is0 = 1.f / s; n = 12;
    } else {
        float cur = sqrtf(d2); n = 0;
        while (cur > 1e-7f && n < 7) { cur = 1.3f * cur * cur; ++n; }
    }
#pragma unroll
    for (int q = 0; q < 8; ++q) {
        int idx = q * 32 + lane; int r = idx >> 4, c = idx & 15;
        Y[idx] = A[idx] * is0;
        Z[idx] = (r == c) ? 1.f : 0.f;
    }
    __syncwarp();
    float* y = Y; float* z = Z; float* y2 = Y2; float* z2 = Z2;
    for (int it = 0; it < n; ++it) {
        wmm16(T, z, y, lane);
#pragma unroll
        for (int q = 0; q < 8; ++q) {
            int idx = q * 32 + lane; int r = idx >> 4, c = idx & 15;
            T[idx] = 0.5f * ((r == c ? 3.f : 0.f) - T[idx]);
        }
        __syncwarp();
        wmm16(y2, y, T, lane);
        wmm16(z2, T, z, lane);
        float* tm = y; y = y2; y2 = tm;
        tm = z; z = z2; z2 = tm;
    }
    float fs = sqrtf(s), fi = rsqrtf(s);
    float ry[8], rz[8];
#pragma unroll
    for (int q = 0; q < 8; ++q) { int idx = q * 32 + lane; ry[q] = y[idx] * fs; rz[q] = z[idx] * fi; }
    __syncwarp();
#pragma unroll
    for (int q = 0; q < 8; ++q) { int idx = q * 32 + lane; Y[idx] = ry[q]; Z[idx] = rz[q]; }
    __syncwarp();
}

// logm(B) in place: logm(B) = ln(s) I + Mercator(B/s - I).
__device__ void w_logm(float* B, float* t1, float* t2, float* t3,
                       float* t4, float* t5, int lane) {
    int jsq = 0; float s, d2;
    for (;;) {
        s = w_trace16(B, lane) * (1.f / 16.f);
        float is = 1.f / s; d2 = 0.f;
#pragma unroll
        for (int q = 0; q < 8; ++q) {
            int idx = q * 32 + lane; int r = idx >> 4, c = idx & 15;
            float v = B[idx] * is - (r == c ? 1.f : 0.f);
            t1[idx] = v; d2 += v * v;
        }
        __syncwarp();
        d2 = wsum32(d2);
        if (d2 <= 0.25f || jsq >= 4) break;
        w_sqrtinv(B, t2, t3, t4, t5, t1, lane);
        float r8[8];
#pragma unroll
        for (int q = 0; q < 8; ++q) r8[q] = t2[q * 32 + lane];
        __syncwarp();
#pragma unroll
        for (int q = 0; q < 8; ++q) B[q * 32 + lane] = r8[q];
        __syncwarp();
        ++jsq;
    }
    float d = sqrtf(d2);
    int nt = 1; { float r = d; while (r > 1e-7f && nt < 24) { r *= d; ++nt; } }
    float lns = logf(s);
#pragma unroll
    for (int q = 0; q < 8; ++q) {
        int idx = q * 32 + lane; int r = idx >> 4, c = idx & 15;
        float v = t1[idx];
        B[idx] = (r == c ? lns : 0.f) + v;
        t2[idx] = v;
    }
    __syncwarp();
    float* P = t2; float* P2 = t3; float sg = 1.f;
    for (int k = 2; k <= nt; ++k) {
        wmm16(P2, P, t1, lane);
        sg = -sg; float cf = sg / (float)k;
#pragma unroll
        for (int q = 0; q < 8; ++q) { int idx = q * 32 + lane; B[idx] += cf * P2[idx]; }
        __syncwarp();
        float* tm = P; P = P2; P2 = tm;
    }
    if (jsq) {
        float f = (float)(1 << jsq);
#pragma unroll
        for (int q = 0; q < 8; ++q) B[q * 32 + lane] *= f;
        __syncwarp();
    }
}

// R = expm(A): expm(A) = e^c expm(A - cI). A preserved.
__device__ void w_expm(const float* A, float* R, float* t1, float* t2, float* t3, int lane) {
    float c0 = w_trace16(A, lane) * (1.f / 16.f);
    float d2 = 0.f;
#pragma unroll
    for (int q = 0; q < 8; ++q) {
        int idx = q * 32 + lane; int r = idx >> 4, c = idx & 15;
        float v = A[idx] - (r == c ? c0 : 0.f);
        t1[idx] = v; d2 += v * v;
    }
    __syncwarp();
    d2 = wsum32(d2);
    int j = 0; float sc = 1.f;
    while (d2 > 0.25f && j < 20) { sc *= 0.5f; d2 *= 0.25f; ++j; }
    if (j) {
#pragma unroll
        for (int q = 0; q < 8; ++q) t1[q * 32 + lane] *= sc;
        __syncwarp();
    }
    float d = sqrtf(d2);
    int nt = 1; { float r = d; while (r > 1e-7f && nt < 14) { ++nt; r *= d / (float)nt; } }
    float ec = expf(c0 * sc);
#pragma unroll
    for (int q = 0; q < 8; ++q) {
        int idx = q * 32 + lane; int r = idx >> 4, c = idx & 15;
        float v = t1[idx];
        R[idx] = (r == c ? 1.f : 0.f) + v;
        t2[idx] = v;
    }
    __syncwarp();
    float* P = t2; float* P2 = t3;
    for (int k = 2; k <= nt; ++k) {
        wmm16(P2, P, t1, lane);
        float ik = 1.f / (float)k;
#pragma unroll
        for (int q = 0; q < 8; ++q) { int idx = q * 32 + lane; float v = P2[idx] * ik; P2[idx] = v; R[idx] += v; }
        __syncwarp();
        float* tm = P; P = P2; P2 = tm;
    }
#pragma unroll
    for (int q = 0; q < 8; ++q) R[q * 32 + lane] *= ec;
    __syncwarp();
    for (int q2 = 0; q2 < j; ++q2) {
        wmm16(t2, R, R, lane);
#pragma unroll
        for (int q = 0; q < 8; ++q) R[q * 32 + lane] = t2[q * 32 + lane];
        __syncwarp();
    }
}

// =========================================================================
// K3: warp0: (Gs,Gi)=sqrt/invsqrt(G=mean_b xmean_b) || warp1: (As,Ai) of rm
// =========================================================================
__global__ __launch_bounds__(64) void k_prep(const float* __restrict__ rm) {
    __shared__ __align__(16) float ws[2][6][256];
    int t = threadIdx.x, w = t >> 5, lane = t & 31;
    float* b0 = ws[w][0]; float* b1 = ws[w][1]; float* b2 = ws[w][2];
    float* b3 = ws[w][3]; float* b4 = ws[w][4]; float* b5 = ws[w][5];
    if (w == 0) {
#pragma unroll
        for (int q = 0; q < 8; ++q) {
            int idx = q * 32 + lane;
            float acc = 0.f;
#pragma unroll 8
            for (int b = 0; b < S_N; ++b) acc += g_xmean[b * NE + idx];
            b0[idx] = acc * (1.f / (float)S_N);
        }
        __syncwarp();
        w_sqrtinv(b0, b1, b2, b3, b4, b5, lane);
#pragma unroll
        for (int q = 0; q < 8; ++q) { int idx = q * 32 + lane; g_Gs[idx] = b1[idx]; g_Gi[idx] = b2[idx]; }
    } else {
#pragma unroll
        for (int q = 0; q < 8; ++q) { int idx = q * 32 + lane; b0[idx] = rm[idx]; }
        __syncwarp();
        w_sqrtinv(b0, b1, b2, b3, b4, b5, lane);
#pragma unroll
        for (int q = 0; q < 8; ++q) { int idx = q * 32 + lane; g_As[idx] = b1[idx]; g_Ai[idx] = b2[idx]; }
    }
}

// =========================================================================
// K4: L_b = logm(Gi * xmean_b * Gi); 32 one-warp blocks in parallel.
// =========================================================================
__global__ __launch_bounds__(32) void k_logm() {
    __shared__ __align__(16) float m[6][256];
    int b = blockIdx.x, lane = threadIdx.x;
#pragma unroll
    for (int q = 0; q < 8; ++q) {
        int idx = q * 32 + lane;
        m[0][idx] = g_Gi[idx];
        m[1][idx] = g_xmean[b * NE + idx];
    }
    __syncwarp();
    wmm16(m[2], m[0], m[1], lane);
    wmm16(m[3], m[2], m[0], lane);
    w_logm(m[3], m[0], m[1], m[2], m[4], m[5], lane);
#pragma unroll
    for (int q = 0; q < 8; ++q) { int idx = q * 32 + lane; g_L[b * NE + idx] = m[3][idx]; }
}

// =========================================================================
// K5: mean = Gs expm(mean L) Gs; then warp0: C = invsqrt(mean) -> g_C
//     || warp1: geodesic(rm, mean, 0.1) -> out tail.
// =========================================================================
__global__ __launch_bounds__(64) void k_finish(float* __restrict__ out_tail, int write_tail) {
    __shared__ __align__(16) float ws[2][6][256];
    __shared__ __align__(16) float sMean[256];
    int t = threadIdx.x, w = t >> 5, lane = t & 31;
    float* b0 = ws[w][0]; float* b1 = ws[w][1]; float* b2 = ws[w][2];
    float* b3 = ws[w][3]; float* b4 = ws[w][4]; float* b5 = ws[w][5];
    if (w == 0) {
#pragma unroll
        for (int q = 0; q < 8; ++q) {
            int idx = q * 32 + lane;
            float acc = 0.f;
#pragma unroll 8
            for (int b = 0; b < S_N; ++b) acc += g_L[b * NE + idx];
            b0[idx] = acc * (1.f / (float)S_N);
        }
        __syncwarp();
        w_expm(b0, b1, b2, b3, b4, lane);         // b1 = expm(Lbar)
        {
#pragma unroll
            for (int q = 0; q < 8; ++q) { int idx = q * 32 + lane; b2[idx] = g_Gs[idx]; }
            __syncwarp();
        }
        wmm16(b3, b2, b1, lane);
        wmm16(sMean, b3, b2, lane);               // Karcher mean
    }
    __syncthreads();
    if (w == 0) {
        w_sqrtinv(sMean, b0, b1, b2, b3, b4, lane);
#pragma unroll
        for (int q = 0; q < 8; ++q) { int idx = q * 32 + lane; g_C[idx] = b1[idx]; }
    } else {
#pragma unroll
        for (int q = 0; q < 8; ++q) { int idx = q * 32 + lane; b0[idx] = g_Ai[idx]; }
        __syncwarp();
        wmm16(b1, b0, sMean, lane);
        wmm16(b2, b1, b0, lane);                  // M = Ai mean Ai
        w_logm(b2, b0, b1, b3, b4, b5, lane);
#pragma unroll
        for (int q = 0; q < 8; ++q) b2[q * 32 + lane] *= 0.1f;
        __syncwarp();
        w_expm(b2, b0, b1, b3, b4, lane);         // b0 = M^0.1
#pragma unroll
        for (int q = 0; q < 8; ++q) { int idx = q * 32 + lane; b1[idx] = g_As[idx]; }
        __syncwarp();
        wmm16(b3, b1, b0, lane);
        wmm16(b4, b3, b1, lane);                  // new running mean
        if (write_tail) {
#pragma unroll
            for (int q = 0; q < 8; ++q) { int idx = q * 32 + lane; out_tail[idx] = b4[idx]; }
        }
    }
}

// =========================================================================
// K6: Y = (C*X)*C. 2 rows per thread, 8 threads/matrix, 32 matrices/block.
// Phase 1 reads X rows from padded smem (4 LDS.128/k shared by 2 rows).
// Phase 2 reads C rows (uniform broadcast, 4 LDS.128/k shared by 2 rows).
// =========================================================================
typedef unsigned long long u64;
__device__ __forceinline__ u64 pk2(float lo, float hi) {
    u64 r; asm("mov.b64 %0, {%1, %2};" : "=l"(r) : "f"(lo), "f"(hi)); return r;
}
__device__ __forceinline__ void upk2(u64 v, float& lo, float& hi) {
    asm("mov.b64 {%0, %1}, %2;" : "=f"(lo), "=f"(hi) : "l"(v));
}
__device__ __forceinline__ u64 ffma2(u64 a, u64 b, u64 c) {
    u64 d; asm("fma.rn.f32x2 %0, %1, %2, %3;" : "=l"(d) : "l"(a), "l"(b), "l"(c)); return d;
}

#define TMPB   32     // matrices per block
#define XSTR4  66     // per-matrix float4 stride in smem (264 floats: bank-skew 8)

__global__ __launch_bounds__(256) void k_transform(const float* __restrict__ X,
                                                   float* __restrict__ Y) {
    __shared__ float4 Xs[TMPB * XSTR4];   // 33 KB
    __shared__ float  Cs[256];
    int t = threadIdx.x;
    Cs[t] = g_C[t];

    const float4* xg = (const float4*)(X + (size_t)blockIdx.x * (TMPB * NE));
#pragma unroll
    for (int j = 0; j < 8; ++j) {
        int g = t + 256 * j;
        Xs[(g >> 6) * XSTR4 + (g & 63)] = xg[g];
    }
    __syncthreads();

    int m = t >> 3, p = t & 7;
    int r0 = 2 * p, r1 = r0 + 1;
    const float4* xm = Xs + m * XSTR4;

    // own C rows as scalars
    float c0[16], c1[16];
    {
        const float4* cp0 = (const float4*)(Cs + r0 * 16);
        const float4* cp1 = (const float4*)(Cs + r1 * 16);
#pragma unroll
        for (int q = 0; q < 4; ++q) {
            float4 a = cp0[q]; float4 b = cp1[q];
            c0[4 * q] = a.x; c0[4 * q + 1] = a.y; c0[4 * q + 2] = a.z; c0[4 * q + 3] = a.w;
            c1[4 * q] = b.x; c1[4 * q + 1] = b.y; c1[4 * q + 2] = b.z; c1[4 * q + 3] = b.w;
        }
    }

    // phase 1: Z rows r0, r1 of Z = C * X
    u64 z0[8], z1[8];
#pragma unroll
    for (int q = 0; q < 8; ++q) { z0[q] = pk2(0.f, 0.f); z1[q] = pk2(0.f, 0.f); }
#pragma unroll
    for (int k = 0; k < 16; ++k) {
        float4 a = xm[k * 4], b = xm[k * 4 + 1], c = xm[k * 4 + 2], d = xm[k * 4 + 3];
        u64 xr[8] = {pk2(a.x, a.y), pk2(a.z, a.w), pk2(b.x, b.y), pk2(b.z, b.w),
                     pk2(c.x, c.y), pk2(c.z, c.w), pk2(d.x, d.y), pk2(d.z, d.w)};
        u64 s0 = pk2(c0[k], c0[k]);
        u64 s1 = pk2(c1[k], c1[k]);
#pragma unroll
        for (int q = 0; q < 8; ++q) {
            z0[q] = ffma2(s0, xr[q], z0[q]);
            z1[q] = ffma2(s1, xr[q], z1[q]);
        }
    }
    float zf0[16], zf1[16];
#pragma unroll
    for (int q = 0; q < 8; ++q) {
        upk2(z0[q], zf0[2 * q], zf0[2 * q + 1]);
        upk2(z1[q], zf1[2 * q], zf1[2 * q + 1]);
    }

    // phase 2: Y rows = Z rows * C   (C rows broadcast from shared)
    u64 y0[8], y1[8];
#pragma unroll
    for (int q = 0; q < 8; ++q) { y0[q] = pk2(0.f, 0.f); y1[q] = pk2(0.f, 0.f); }
#pragma unroll
    for (int k = 0; k < 16; ++k) {
        const float4* cr4 = (const float4*)(Cs + k * 16);
        float4 a = cr4[0], b = cr4[1], c = cr4[2], d = cr4[3];
        u64 cu[8] = {pk2(a.x, a.y), pk2(a.z, a.w), pk2(b.x, b.y), pk2(b.z, b.w),
                     pk2(c.x, c.y), pk2(c.z, c.w), pk2(d.x, d.y), pk2(d.z, d.w)};
        u64 s0 = pk2(zf0[k], zf0[k]);
        u64 s1 = pk2(zf1[k], zf1[k]);
#pragma unroll
        for (int q = 0; q < 8; ++q) {
            y0[q] = ffma2(s0, cu[q], y0[q]);
            y1[q] = ffma2(s1, cu[q], y1[q]);
        }
    }

    float4* yg = (float4*)(Y + (size_t)blockIdx.x * (TMPB * NE) + (size_t)m * NE);
#pragma unroll
    for (int q = 0; q < 4; ++q) {
        float4 v0, v1;
        upk2(y0[2 * q], v0.x, v0.y); upk2(y0[2 * q + 1], v0.z, v0.w);
        upk2(y1[2 * q], v1.x, v1.y); upk2(y1[2 * q + 1], v1.z, v1.w);
        yg[r0 * 4 + q] = v0;
        yg[r1 * 4 + q] = v1;
    }
}

// =========================================================================
extern "C" void kernel_launch(void* const* d_in, const int* in_sizes, int n_in,
                              void* d_out, int out_size) {
    const float* X = (const float*)d_in[0];
    const float* rm = (const float*)d_in[1];
    float* out = (float*)d_out;
    long long n_x = in_sizes[0];           // 26,214,400
    int nmat = (int)(n_x >> 8);            // 102,400
    int write_tail = ((long long)out_size - n_x) >= NE ? 1 : 0;

    k_partial<<<dim3(S_N, CHUNKS), 256>>>(X);
    k_samplemean<<<S_N, 256>>>();
    k_prep<<<1, 64>>>(rm);
    k_logm<<<S_N, 32>>>();
    k_finish<<<1, 64>>>(out + n_x, write_tail);
    k_transform<<<nmat / TMPB, 256>>>(X, out);
}